// round 3
// baseline (speedup 1.0000x reference)
#include <cuda_runtime.h>

// PINODEv3: persistent RK4 neural-ODE integrator.
// One kernel launch. Each CTA owns Mr=16 batch rows and integrates the full
// 31-step RK4 trajectory locally (batches are independent; weights read-only).
// fp32 baseline: thread j <-> hidden column j; Wh streamed from L2 with
// coalesced column loads, register-blocked over the 16 rows.
// R1 fix: hbuf must be 16B-aligned for the float4 shared loads.

constexpr int Bn   = 8192;
constexpr int Tn   = 32;
constexpr int Hn   = 256;
constexpr int NLm1 = 3;     // NL-1 hidden matmul layers
constexpr int Mr   = 16;    // batch rows per CTA
constexpr int NT   = 256;   // threads per CTA (= Hn)
#define EPSf 1e-5f

__global__ void __launch_bounds__(NT, 4) pinode_rk4_kernel(
    const float* __restrict__ y0,
    const float* __restrict__ t_span,
    const float* __restrict__ params,
    const float* __restrict__ W0,
    const float* __restrict__ b0,
    const float* __restrict__ Wh,
    const float* __restrict__ bh,
    const float* __restrict__ ln_g,
    const float* __restrict__ ln_b,
    const float* __restrict__ Wout,
    const float* __restrict__ bout,
    const float* __restrict__ gatep,
    float* __restrict__ out)
{
    __shared__ float sW0[6 * Hn];          // 6x256
    __shared__ float sb0[Hn];
    __shared__ float sbh[NLm1 * Hn];
    __shared__ float sg[4 * Hn];           // ln_g, 4 layers
    __shared__ float sbt[4 * Hn];          // ln_b
    __shared__ float sWout[Hn * 3];
    __shared__ float sbout[3];
    __shared__ float sts[Tn];
    __shared__ alignas(16) float hbuf[Mr][Hn + 4];  // padded rows, float4 loads
    __shared__ float ysm[Mr][3];
    __shared__ float psm[Mr][3];
    __shared__ float yin[Mr][3];
    __shared__ float kcur[Mr][3];
    __shared__ float kacc[Mr][3];
    __shared__ float smu[Mr], srs[Mr];
    __shared__ float sgate;

    const int tid  = threadIdx.x;
    const int lane = tid & 31;
    const int wid  = tid >> 5;
    const int row0 = blockIdx.x * Mr;
    const int j    = tid;                  // hidden column owned by this thread

    // ---- preload small params into smem ----
    for (int i = tid; i < 6 * Hn; i += NT) sW0[i] = W0[i];
    for (int i = tid; i < Hn; i += NT)     sb0[i] = b0[i];
    for (int i = tid; i < NLm1 * Hn; i += NT) sbh[i] = bh[i];
    for (int i = tid; i < 4 * Hn; i += NT) { sg[i] = ln_g[i]; sbt[i] = ln_b[i]; }
    for (int i = tid; i < Hn * 3; i += NT) sWout[i] = Wout[i];
    if (tid < 3)  sbout[tid] = bout[tid];
    if (tid < Tn) sts[tid]  = t_span[tid];
    if (tid == 0) sgate = gatep[0];
    if (tid < Mr * 3) {
        int m = tid / 3, c = tid % 3;
        float v = y0[(row0 + m) * 3 + c];
        ysm[m][c] = v;
        psm[m][c] = params[(row0 + m) * 3 + c];
        out[(size_t)(row0 + m) * 3 + c] = v;   // t = 0 row of output
    }
    __syncthreads();

    const float gate = sgate;

    // LayerNorm(+SiLU) over the current register accumulators `acc`,
    // writing the activated values into hbuf. Lidx selects ln_g/ln_b row.
    auto ln_silu = [&](float* acc, int Lidx) {
        __syncthreads();                       // prior hbuf readers done
        #pragma unroll
        for (int m = 0; m < Mr; m++) hbuf[m][j] = acc[m];
        __syncthreads();
        // per-row stats: each warp reduces 2 rows
        for (int m = wid; m < Mr; m += 8) {
            float s = 0.f, s2 = 0.f;
            #pragma unroll
            for (int i = 0; i < Hn / 32; i++) {
                float v = hbuf[m][lane + 32 * i];
                s += v;
                s2 = fmaf(v, v, s2);
            }
            #pragma unroll
            for (int o = 16; o; o >>= 1) {
                s  += __shfl_xor_sync(0xFFFFFFFFu, s,  o);
                s2 += __shfl_xor_sync(0xFFFFFFFFu, s2, o);
            }
            if (lane == 0) {
                float mu  = s * (1.f / Hn);
                float var = s2 * (1.f / Hn) - mu * mu;
                smu[m] = mu;
                srs[m] = rsqrtf(var + EPSf);
            }
        }
        __syncthreads();
        float g  = sg[Lidx * Hn + j];
        float bt = sbt[Lidx * Hn + j];
        #pragma unroll
        for (int m = 0; m < Mr; m++) {
            float v = fmaf((acc[m] - smu[m]) * srs[m], g, bt);
            v = v / (1.f + __expf(-v));        // SiLU
            hbuf[m][j] = v;
        }
        __syncthreads();
    };

    // f_total(yin) -> kcur   (bloch RHS + gate * correction_net)
    auto eval_f = [&]() {
        float acc[Mr];
        // layer 0: x = [y(3), p(3)] @ W0 + b0
        #pragma unroll
        for (int m = 0; m < Mr; m++) acc[m] = sb0[j];
        #pragma unroll
        for (int k = 0; k < 3; k++) {
            float w = sW0[k * Hn + j];
            #pragma unroll
            for (int m = 0; m < Mr; m++) acc[m] = fmaf(yin[m][k], w, acc[m]);
        }
        #pragma unroll
        for (int k = 0; k < 3; k++) {
            float w = sW0[(k + 3) * Hn + j];
            #pragma unroll
            for (int m = 0; m < Mr; m++) acc[m] = fmaf(psm[m][k], w, acc[m]);
        }
        ln_silu(acc, 0);

        // hidden layers: h = silu(ln(h @ Wh[L] + bh[L]))
        for (int L = 0; L < NLm1; L++) {
            const float* wb = Wh + (size_t)L * Hn * Hn + j;
            #pragma unroll
            for (int m = 0; m < Mr; m++) acc[m] = sbh[L * Hn + j];
            #pragma unroll 2
            for (int k = 0; k < Hn; k += 4) {
                float w0 = __ldg(wb + (size_t)(k + 0) * Hn);
                float w1 = __ldg(wb + (size_t)(k + 1) * Hn);
                float w2 = __ldg(wb + (size_t)(k + 2) * Hn);
                float w3 = __ldg(wb + (size_t)(k + 3) * Hn);
                #pragma unroll
                for (int m = 0; m < Mr; m++) {
                    float4 hv = *reinterpret_cast<const float4*>(&hbuf[m][k]);
                    acc[m] = fmaf(hv.x, w0, acc[m]);
                    acc[m] = fmaf(hv.y, w1, acc[m]);
                    acc[m] = fmaf(hv.z, w2, acc[m]);
                    acc[m] = fmaf(hv.w, w3, acc[m]);
                }
            }
            ln_silu(acc, L + 1);
        }

        // output projection (256 -> 3) + bloch RHS, per-warp row reduction
        for (int m = wid; m < Mr; m += 8) {
            float s0 = 0.f, s1 = 0.f, s2 = 0.f;
            #pragma unroll
            for (int i = 0; i < Hn / 32; i++) {
                int jj = lane + 32 * i;
                float hv = hbuf[m][jj];
                s0 = fmaf(hv, sWout[jj * 3 + 0], s0);
                s1 = fmaf(hv, sWout[jj * 3 + 1], s1);
                s2 = fmaf(hv, sWout[jj * 3 + 2], s2);
            }
            #pragma unroll
            for (int o = 16; o; o >>= 1) {
                s0 += __shfl_xor_sync(0xFFFFFFFFu, s0, o);
                s1 += __shfl_xor_sync(0xFFFFFFFFu, s1, o);
                s2 += __shfl_xor_sync(0xFFFFFFFFu, s2, o);
            }
            if (lane == 0) {
                float u = yin[m][0], v = yin[m][1], w = yin[m][2];
                float Om = psm[m][0], ga = psm[m][2];
                kcur[m][0] = fmaf(gate, s0 + sbout[0], -ga * u);
                kcur[m][1] = fmaf(gate, s1 + sbout[1], -ga * v - Om * w);
                kcur[m][2] = fmaf(gate, s2 + sbout[2], -2.f * ga * (w + 1.f) + Om * v);
            }
        }
        __syncthreads();
    };

    // ---- RK4 time loop ----
    for (int t = 0; t < Tn - 1; t++) {
        float dt = sts[t + 1] - sts[t];

        // stage 1
        if (tid < Mr * 3) {
            int m = tid / 3, c = tid % 3;
            yin[m][c] = ysm[m][c];
        }
        __syncthreads();
        eval_f();
        if (tid < Mr * 3) {
            int m = tid / 3, c = tid % 3;
            float k1 = kcur[m][c];
            kacc[m][c] = k1;
            yin[m][c] = fmaf(0.5f * dt, k1, ysm[m][c]);
        }
        __syncthreads();

        // stage 2
        eval_f();
        if (tid < Mr * 3) {
            int m = tid / 3, c = tid % 3;
            float k2 = kcur[m][c];
            kacc[m][c] += 2.f * k2;
            yin[m][c] = fmaf(0.5f * dt, k2, ysm[m][c]);
        }
        __syncthreads();

        // stage 3
        eval_f();
        if (tid < Mr * 3) {
            int m = tid / 3, c = tid % 3;
            float k3 = kcur[m][c];
            kacc[m][c] += 2.f * k3;
            yin[m][c] = fmaf(dt, k3, ysm[m][c]);
        }
        __syncthreads();

        // stage 4 + update + store
        eval_f();
        if (tid < Mr * 3) {
            int m = tid / 3, c = tid % 3;
            float ksum = kacc[m][c] + kcur[m][c];
            float yn = fmaf(dt * (1.f / 6.f), ksum, ysm[m][c]);
            ysm[m][c] = yn;
            out[((size_t)(t + 1) * Bn + row0 + m) * 3 + c] = yn;
        }
        __syncthreads();
    }
}

extern "C" void kernel_launch(void* const* d_in, const int* in_sizes, int n_in,
                              void* d_out, int out_size) {
    (void)in_sizes; (void)n_in; (void)out_size;
    pinode_rk4_kernel<<<Bn / Mr, NT>>>(
        (const float*)d_in[0],   // y0
        (const float*)d_in[1],   // t_span
        (const float*)d_in[2],   // params
        (const float*)d_in[3],   // W0
        (const float*)d_in[4],   // b0
        (const float*)d_in[5],   // Wh
        (const float*)d_in[6],   // bh
        (const float*)d_in[7],   // ln_g
        (const float*)d_in[8],   // ln_b
        (const float*)d_in[9],   // Wout
        (const float*)d_in[10],  // bout
        (const float*)d_in[11],  // gate
        (float*)d_out);
}

// round 4
// speedup vs baseline: 2.2366x; 2.2366x over previous
#include <cuda_runtime.h>
#include <cstdint>

// PINODEv3 persistent RK4 integrator, TF32 tensor-core hidden layers.
// Mr=32 batch rows per CTA, 8 warps. Hidden GEMMs (32x256 @ 256x256) via
// mma.sync.m16n8k8.tf32 with fp32 accumulators. Weight k-tiles double-buffered
// in smem via cp.async. Layer0 / LN / SiLU / output proj / Bloch / RK4 in fp32.

constexpr int Bn   = 8192;
constexpr int Tn   = 32;
constexpr int Hn   = 256;
constexpr int NLm1 = 3;
constexpr int Mr   = 32;     // batch rows per CTA
constexpr int NT   = 256;    // 8 warps
constexpr int HP   = Hn + 4; // hbuf row stride (260: 4g+t bank-unique)
constexpr int WP   = Hn + 8; // W tile row stride (264: conflict-free B frags)
constexpr int NK   = Hn / 8; // 32 k-steps
#define EPSf 1e-5f

__device__ float g_WhR[NLm1 * Hn * Hn];   // tf32-rounded weights scratch

__device__ __forceinline__ uint32_t cvt_tf32(float x) {
    uint32_t u;
    asm("cvt.rna.tf32.f32 %0, %1;" : "=r"(u) : "f"(x));
    return u;
}
__device__ __forceinline__ void cp16(uint32_t dst, const float* src) {
    asm volatile("cp.async.ca.shared.global [%0], [%1], 16;" :: "r"(dst), "l"(src));
}
__device__ __forceinline__ void cp_commit() {
    asm volatile("cp.async.commit_group;" ::: "memory");
}
__device__ __forceinline__ void cp_wait0() {
    asm volatile("cp.async.wait_group 0;" ::: "memory");
}
__device__ __forceinline__ void mma_tf32(float& c0, float& c1, float& c2, float& c3,
                                         uint32_t a0, uint32_t a1, uint32_t a2, uint32_t a3,
                                         uint32_t b0, uint32_t b1) {
    asm volatile(
        "mma.sync.aligned.m16n8k8.row.col.f32.tf32.tf32.f32 "
        "{%0,%1,%2,%3}, {%4,%5,%6,%7}, {%8,%9}, {%0,%1,%2,%3};"
        : "+f"(c0), "+f"(c1), "+f"(c2), "+f"(c3)
        : "r"(a0), "r"(a1), "r"(a2), "r"(a3), "r"(b0), "r"(b1));
}

__global__ void round_wh_kernel(const float* __restrict__ Wh, int n) {
    int i = blockIdx.x * blockDim.x + threadIdx.x;
    if (i < n) g_WhR[i] = __uint_as_float(cvt_tf32(Wh[i]));
}

__global__ void __launch_bounds__(NT, 2) pinode_rk4_tc_kernel(
    const float* __restrict__ y0,
    const float* __restrict__ t_span,
    const float* __restrict__ params,
    const float* __restrict__ W0,
    const float* __restrict__ b0,
    const float* __restrict__ bh,
    const float* __restrict__ ln_g,
    const float* __restrict__ ln_b,
    const float* __restrict__ Wout,
    const float* __restrict__ bout,
    const float* __restrict__ gatep,
    float* __restrict__ out)
{
    __shared__ float sW0[6 * Hn];
    __shared__ float sb0[Hn];
    __shared__ float sbh[NLm1 * Hn];
    __shared__ float sg[4 * Hn];
    __shared__ float sbt[4 * Hn];
    __shared__ float sWout[Hn * 3];
    __shared__ float sbout[3];
    __shared__ float sts[Tn];
    __shared__ alignas(16) float hbuf[Mr][HP];       // activations, 33.3 KB
    __shared__ alignas(16) float sWt[2][8 * WP];     // W k-tiles, 2 x 8.25 KB
    __shared__ float ysm[Mr][3], psm[Mr][3], yin[Mr][3];
    __shared__ float kcur[Mr][3], kacc[Mr][3];
    __shared__ float smu[Mr], srs[Mr];
    __shared__ float sgate;

    const int tid  = threadIdx.x;
    const int lane = tid & 31;
    const int wid  = tid >> 5;
    const int g8   = lane >> 2;   // 0..7
    const int t4   = lane & 3;    // 0..3
    const int row0 = blockIdx.x * Mr;
    const int j    = tid;         // hidden column for elementwise phases

    // smem base addresses for cp.async
    const uint32_t sWt_u32 = (uint32_t)__cvta_generic_to_shared(&sWt[0][0]);
    const uint32_t stage_off = (uint32_t)(((tid >> 5) * WP + (tid & 31) * 8) * 4);
    const uint32_t buf_stride = (uint32_t)(8 * WP * 4);

    // ---- preload params ----
    for (int i = tid; i < 6 * Hn; i += NT) sW0[i] = W0[i];
    for (int i = tid; i < Hn; i += NT)     sb0[i] = b0[i];
    for (int i = tid; i < NLm1 * Hn; i += NT) sbh[i] = bh[i];
    for (int i = tid; i < 4 * Hn; i += NT) { sg[i] = ln_g[i]; sbt[i] = ln_b[i]; }
    for (int i = tid; i < Hn * 3; i += NT) sWout[i] = Wout[i];
    if (tid < 3)  sbout[tid] = bout[tid];
    if (tid < Tn) sts[tid]  = t_span[tid];
    if (tid == 0) sgate = gatep[0];
    for (int i = tid; i < Mr * 3; i += NT) {
        int m = i / 3, c = i % 3;
        float v = y0[(row0 + m) * 3 + c];
        ysm[m][c] = v;
        psm[m][c] = params[(row0 + m) * 3 + c];
        out[(size_t)(row0 + m) * 3 + c] = v;
    }
    __syncthreads();

    const float gate = sgate;

    // ---- LayerNorm + SiLU in-place on hbuf ----
    auto ln_silu = [&](int Lidx) {
        __syncthreads();    // hbuf writes visible
        for (int m = wid; m < Mr; m += 8) {
            float s = 0.f, s2 = 0.f;
            #pragma unroll
            for (int i = 0; i < Hn / 32; i++) {
                float v = hbuf[m][lane + 32 * i];
                s += v;
                s2 = fmaf(v, v, s2);
            }
            #pragma unroll
            for (int o = 16; o; o >>= 1) {
                s  += __shfl_xor_sync(0xFFFFFFFFu, s,  o);
                s2 += __shfl_xor_sync(0xFFFFFFFFu, s2, o);
            }
            if (lane == 0) {
                float mu  = s * (1.f / Hn);
                float var = s2 * (1.f / Hn) - mu * mu;
                smu[m] = mu;
                srs[m] = rsqrtf(var + EPSf);
            }
        }
        __syncthreads();
        float gg = sg[Lidx * Hn + j];
        float bb = sbt[Lidx * Hn + j];
        #pragma unroll 4
        for (int m = 0; m < Mr; m++) {
            float v = fmaf((hbuf[m][j] - smu[m]) * srs[m], gg, bb);
            hbuf[m][j] = v / (1.f + __expf(-v));
        }
        __syncthreads();
    };

    // ---- stage one 8x256 weight k-tile into smem buffer p ----
    auto stage = [&](const float* Wg, int kt, int p) {
        const float* src = Wg + kt * 8 * Hn + (tid >> 5) * Hn + (tid & 31) * 8;
        uint32_t dst = sWt_u32 + (uint32_t)p * buf_stride + stage_off;
        cp16(dst, src);
        cp16(dst + 16, src + 4);
        cp_commit();
    };

    // ---- hidden layer L: hbuf = silu(ln(hbuf @ Wh[L] + bh[L])) ----
    auto hidden_layer = [&](int L) {
        const float* Wg = g_WhR + (size_t)L * Hn * Hn;
        const int nbase = 32 * wid;

        // C fragments [mtile][ntile][reg], init with bias
        float c[2][4][4];
        #pragma unroll
        for (int t = 0; t < 4; t++) {
            float bA = sbh[L * Hn + nbase + 8 * t + 2 * t4];
            float bB = sbh[L * Hn + nbase + 8 * t + 2 * t4 + 1];
            #pragma unroll
            for (int i = 0; i < 2; i++) {
                c[i][t][0] = bA; c[i][t][1] = bB;
                c[i][t][2] = bA; c[i][t][3] = bB;
            }
        }

        stage(Wg, 0, 0);
        for (int kt = 0; kt < NK; kt++) {
            cp_wait0();
            __syncthreads();
            if (kt + 1 < NK) stage(Wg, kt + 1, (kt + 1) & 1);

            const int k0 = kt * 8;
            const float* wt = &sWt[kt & 1][0];

            // A fragments (activations, round to tf32)
            uint32_t a[2][4];
            #pragma unroll
            for (int i = 0; i < 2; i++) {
                int r = 16 * i + g8;
                a[i][0] = cvt_tf32(hbuf[r][k0 + t4]);
                a[i][1] = cvt_tf32(hbuf[r + 8][k0 + t4]);
                a[i][2] = cvt_tf32(hbuf[r][k0 + t4 + 4]);
                a[i][3] = cvt_tf32(hbuf[r + 8][k0 + t4 + 4]);
            }
            #pragma unroll
            for (int t = 0; t < 4; t++) {
                int n = nbase + 8 * t + g8;
                uint32_t b0f = *reinterpret_cast<const uint32_t*>(&wt[t4 * WP + n]);
                uint32_t b1f = *reinterpret_cast<const uint32_t*>(&wt[(t4 + 4) * WP + n]);
                #pragma unroll
                for (int i = 0; i < 2; i++)
                    mma_tf32(c[i][t][0], c[i][t][1], c[i][t][2], c[i][t][3],
                             a[i][0], a[i][1], a[i][2], a[i][3], b0f, b1f);
            }
        }
        __syncthreads();    // all A-frag reads done before overwriting hbuf

        // store C fragments back into hbuf
        #pragma unroll
        for (int i = 0; i < 2; i++) {
            #pragma unroll
            for (int t = 0; t < 4; t++) {
                int r  = 16 * i + g8;
                int n  = nbase + 8 * t + 2 * t4;
                *reinterpret_cast<float2*>(&hbuf[r][n])     = make_float2(c[i][t][0], c[i][t][1]);
                *reinterpret_cast<float2*>(&hbuf[r + 8][n]) = make_float2(c[i][t][2], c[i][t][3]);
            }
        }
        ln_silu(L + 1);
    };

    // ---- f_total(yin) -> kcur ----
    auto eval_f = [&]() {
        // layer 0: [y, p] @ W0 + b0 (fp32 scalar, column j per thread)
        float w0r[6];
        #pragma unroll
        for (int k = 0; k < 6; k++) w0r[k] = sW0[k * Hn + j];
        float bj = sb0[j];
        #pragma unroll 4
        for (int m = 0; m < Mr; m++) {
            float v = bj;
            v = fmaf(yin[m][0], w0r[0], v);
            v = fmaf(yin[m][1], w0r[1], v);
            v = fmaf(yin[m][2], w0r[2], v);
            v = fmaf(psm[m][0], w0r[3], v);
            v = fmaf(psm[m][1], w0r[4], v);
            v = fmaf(psm[m][2], w0r[5], v);
            hbuf[m][j] = v;
        }
        ln_silu(0);

        hidden_layer(0);
        hidden_layer(1);
        hidden_layer(2);

        // output projection 256->3 + Bloch RHS
        for (int m = wid; m < Mr; m += 8) {
            float s0 = 0.f, s1 = 0.f, s2 = 0.f;
            #pragma unroll
            for (int i = 0; i < Hn / 32; i++) {
                int jj = lane + 32 * i;
                float hv = hbuf[m][jj];
                s0 = fmaf(hv, sWout[jj * 3 + 0], s0);
                s1 = fmaf(hv, sWout[jj * 3 + 1], s1);
                s2 = fmaf(hv, sWout[jj * 3 + 2], s2);
            }
            #pragma unroll
            for (int o = 16; o; o >>= 1) {
                s0 += __shfl_xor_sync(0xFFFFFFFFu, s0, o);
                s1 += __shfl_xor_sync(0xFFFFFFFFu, s1, o);
                s2 += __shfl_xor_sync(0xFFFFFFFFu, s2, o);
            }
            if (lane == 0) {
                float u = yin[m][0], v = yin[m][1], w = yin[m][2];
                float Om = psm[m][0], ga = psm[m][2];
                kcur[m][0] = fmaf(gate, s0 + sbout[0], -ga * u);
                kcur[m][1] = fmaf(gate, s1 + sbout[1], -ga * v - Om * w);
                kcur[m][2] = fmaf(gate, s2 + sbout[2], -2.f * ga * (w + 1.f) + Om * v);
            }
        }
        __syncthreads();
    };

    // ---- RK4 time loop ----
    for (int t = 0; t < Tn - 1; t++) {
        float dt = sts[t + 1] - sts[t];

        if (tid < Mr * 3) {
            int m = tid / 3, c = tid % 3;
            yin[m][c] = ysm[m][c];
        }
        __syncthreads();
        eval_f();
        if (tid < Mr * 3) {
            int m = tid / 3, c = tid % 3;
            float k1 = kcur[m][c];
            kacc[m][c] = k1;
            yin[m][c] = fmaf(0.5f * dt, k1, ysm[m][c]);
        }
        __syncthreads();

        eval_f();
        if (tid < Mr * 3) {
            int m = tid / 3, c = tid % 3;
            float k2 = kcur[m][c];
            kacc[m][c] += 2.f * k2;
            yin[m][c] = fmaf(0.5f * dt, k2, ysm[m][c]);
        }
        __syncthreads();

        eval_f();
        if (tid < Mr * 3) {
            int m = tid / 3, c = tid % 3;
            float k3 = kcur[m][c];
            kacc[m][c] += 2.f * k3;
            yin[m][c] = fmaf(dt, k3, ysm[m][c]);
        }
        __syncthreads();

        eval_f();
        if (tid < Mr * 3) {
            int m = tid / 3, c = tid % 3;
            float ksum = kacc[m][c] + kcur[m][c];
            float yn = fmaf(dt * (1.f / 6.f), ksum, ysm[m][c]);
            ysm[m][c] = yn;
            out[((size_t)(t + 1) * Bn + row0 + m) * 3 + c] = yn;
        }
        __syncthreads();
    }
}

extern "C" void kernel_launch(void* const* d_in, const int* in_sizes, int n_in,
                              void* d_out, int out_size) {
    (void)in_sizes; (void)n_in; (void)out_size;
    const int nW = NLm1 * Hn * Hn;
    round_wh_kernel<<<(nW + 255) / 256, 256>>>((const float*)d_in[5], nW);
    pinode_rk4_tc_kernel<<<Bn / Mr, NT>>>(
        (const float*)d_in[0],   // y0
        (const float*)d_in[1],   // t_span
        (const float*)d_in[2],   // params
        (const float*)d_in[3],   // W0
        (const float*)d_in[4],   // b0
        (const float*)d_in[6],   // bh
        (const float*)d_in[7],   // ln_g
        (const float*)d_in[8],   // ln_b
        (const float*)d_in[9],   // Wout
        (const float*)d_in[10],  // bout
        (const float*)d_in[11],  // gate
        (float*)d_out);
}

// round 5
// speedup vs baseline: 3.5344x; 1.5803x over previous
#include <cuda_runtime.h>
#include <cstdint>

// PINODEv3 persistent RK4 integrator, TF32 tensor cores, barrier-free K-loop.
// Weights pre-packed into mma B-fragment order so the hidden-layer GEMM is a
// pure warp-private loop: float4 LDG (coalesced) + LDS A-frags + mma, with a
// depth-1 register prefetch. No smem staging, no syncs inside the K-loop.

constexpr int Bn   = 8192;
constexpr int Tn   = 32;
constexpr int Hn   = 256;
constexpr int NLm1 = 3;
constexpr int Mr   = 32;     // batch rows per CTA
constexpr int NT   = 256;    // 8 warps
constexpr int HP   = Hn + 4; // hbuf row stride (260: 4g+t bank-unique for A frags)
#define EPSf 1e-5f

// Packed tf32 weights: [L][kt2(16)][n(256)][t4(4)][e(4)]
//   e0 -> W[16*kt2+t4   ][n]   (khalf0 b0)
//   e1 -> W[16*kt2+t4+4 ][n]   (khalf0 b1)
//   e2 -> W[16*kt2+t4+8 ][n]   (khalf1 b0)
//   e3 -> W[16*kt2+t4+12][n]   (khalf1 b1)
__device__ float g_Wp[NLm1 * Hn * Hn];

__device__ __forceinline__ uint32_t cvt_tf32(float x) {
    uint32_t u;
    asm("cvt.rna.tf32.f32 %0, %1;" : "=r"(u) : "f"(x));
    return u;
}
__device__ __forceinline__ void mma_tf32(float& c0, float& c1, float& c2, float& c3,
                                         uint32_t a0, uint32_t a1, uint32_t a2, uint32_t a3,
                                         uint32_t b0, uint32_t b1) {
    asm volatile(
        "mma.sync.aligned.m16n8k8.row.col.f32.tf32.tf32.f32 "
        "{%0,%1,%2,%3}, {%4,%5,%6,%7}, {%8,%9}, {%0,%1,%2,%3};"
        : "+f"(c0), "+f"(c1), "+f"(c2), "+f"(c3)
        : "r"(a0), "r"(a1), "r"(a2), "r"(a3), "r"(b0), "r"(b1));
}

__global__ void pack_wh_kernel(const float* __restrict__ Wh) {
    int i = blockIdx.x * blockDim.x + threadIdx.x;
    if (i >= NLm1 * Hn * Hn) return;
    int e   = i & 3;
    int t4  = (i >> 2) & 3;
    int n   = (i >> 4) & 255;
    int kt2 = (i >> 12) & 15;
    int L   = i >> 16;
    int r = kt2 * 16 + (e >> 1) * 8 + (e & 1) * 4 + t4;
    g_Wp[i] = __uint_as_float(cvt_tf32(Wh[((size_t)L * Hn + r) * Hn + n]));
}

__global__ void __launch_bounds__(NT, 2) pinode_rk4_tc_kernel(
    const float* __restrict__ y0,
    const float* __restrict__ t_span,
    const float* __restrict__ params,
    const float* __restrict__ W0,
    const float* __restrict__ b0,
    const float* __restrict__ bh,
    const float* __restrict__ ln_g,
    const float* __restrict__ ln_b,
    const float* __restrict__ Wout,
    const float* __restrict__ bout,
    const float* __restrict__ gatep,
    float* __restrict__ out)
{
    __shared__ float sW0[6 * Hn];
    __shared__ float sb0[Hn];
    __shared__ float sbh[NLm1 * Hn];
    __shared__ float sg[4 * Hn];
    __shared__ float sbt[4 * Hn];
    __shared__ float sWout[Hn * 3];
    __shared__ float sbout[3];
    __shared__ float sts[Tn];
    __shared__ alignas(16) float hbuf[Mr][HP];
    __shared__ float ysm[Mr][3], psm[Mr][3], yin[Mr][3];
    __shared__ float kcur[Mr][3], kacc[Mr][3];
    __shared__ float smu[Mr], srs[Mr];
    __shared__ float sgate;

    const int tid  = threadIdx.x;
    const int lane = tid & 31;
    const int wid  = tid >> 5;
    const int g8   = lane >> 2;
    const int t4   = lane & 3;
    const int row0 = blockIdx.x * Mr;
    const int j    = tid;

    // ---- preload params ----
    for (int i = tid; i < 6 * Hn; i += NT) sW0[i] = W0[i];
    for (int i = tid; i < Hn; i += NT)     sb0[i] = b0[i];
    for (int i = tid; i < NLm1 * Hn; i += NT) sbh[i] = bh[i];
    for (int i = tid; i < 4 * Hn; i += NT) { sg[i] = ln_g[i]; sbt[i] = ln_b[i]; }
    for (int i = tid; i < Hn * 3; i += NT) sWout[i] = Wout[i];
    if (tid < 3)  sbout[tid] = bout[tid];
    if (tid < Tn) sts[tid]  = t_span[tid];
    if (tid == 0) sgate = gatep[0];
    for (int i = tid; i < Mr * 3; i += NT) {
        int m = i / 3, c = i % 3;
        float v = y0[(row0 + m) * 3 + c];
        ysm[m][c] = v;
        psm[m][c] = params[(row0 + m) * 3 + c];
        out[(size_t)(row0 + m) * 3 + c] = v;
    }
    __syncthreads();

    const float gate = sgate;

    // ---- LayerNorm + SiLU in-place on hbuf (stores tf32-rounded) ----
    auto ln_silu = [&](int Lidx) {
        __syncthreads();
        for (int m = wid; m < Mr; m += 8) {
            float s = 0.f, s2 = 0.f;
            #pragma unroll
            for (int i = 0; i < Hn / 32; i++) {
                float v = hbuf[m][lane + 32 * i];
                s += v;
                s2 = fmaf(v, v, s2);
            }
            #pragma unroll
            for (int o = 16; o; o >>= 1) {
                s  += __shfl_xor_sync(0xFFFFFFFFu, s,  o);
                s2 += __shfl_xor_sync(0xFFFFFFFFu, s2, o);
            }
            if (lane == 0) {
                float mu  = s * (1.f / Hn);
                float var = s2 * (1.f / Hn) - mu * mu;
                smu[m] = mu;
                srs[m] = rsqrtf(var + EPSf);
            }
        }
        __syncthreads();
        float gg = sg[Lidx * Hn + j];
        float bb = sbt[Lidx * Hn + j];
        #pragma unroll 4
        for (int m = 0; m < Mr; m++) {
            float v = fmaf((hbuf[m][j] - smu[m]) * srs[m], gg, bb);
            v = v / (1.f + __expf(-v));
            hbuf[m][j] = __uint_as_float(cvt_tf32(v));   // pre-round for mma A
        }
        __syncthreads();
    };

    // ---- hidden layer L: hbuf = silu(ln(hbuf @ Wh[L] + bh[L])) ----
    auto hidden_layer = [&](int L) {
        const int nbase = 32 * wid;
        // per-lane base pointer into packed weights (float4 units):
        // idx = ((L*16 + kt2)*256 + n)*4 + t4 ; n-tile t offset = +32, kt2 = +1024
        const float4* Wp = reinterpret_cast<const float4*>(g_Wp)
                         + ((size_t)L * 16 * Hn + (nbase + g8)) * 4 + t4;

        float c[2][4][4];
        #pragma unroll
        for (int t = 0; t < 4; t++) {
            float bA = sbh[L * Hn + nbase + 8 * t + 2 * t4];
            float bB = sbh[L * Hn + nbase + 8 * t + 2 * t4 + 1];
            #pragma unroll
            for (int i = 0; i < 2; i++) {
                c[i][t][0] = bA; c[i][t][1] = bB;
                c[i][t][2] = bA; c[i][t][3] = bB;
            }
        }

        float4 bc[4], bn[4];
        #pragma unroll
        for (int t = 0; t < 4; t++) bc[t] = __ldg(Wp + t * 32);

        #pragma unroll 4
        for (int kt2 = 0; kt2 < 16; kt2++) {
            // depth-1 prefetch of next k-double-tile (predicated off on last)
            if (kt2 + 1 < 16) {
                #pragma unroll
                for (int t = 0; t < 4; t++)
                    bn[t] = __ldg(Wp + (kt2 + 1) * 1024 + t * 32);
            }
            const int k0 = kt2 * 16;

            // ---- khalf 0 (k rows k0+t4, k0+t4+4) ----
            uint32_t a[2][4];
            #pragma unroll
            for (int i = 0; i < 2; i++) {
                int r = 16 * i + g8;
                a[i][0] = __float_as_uint(hbuf[r][k0 + t4]);
                a[i][1] = __float_as_uint(hbuf[r + 8][k0 + t4]);
                a[i][2] = __float_as_uint(hbuf[r][k0 + t4 + 4]);
                a[i][3] = __float_as_uint(hbuf[r + 8][k0 + t4 + 4]);
            }
            #pragma unroll
            for (int t = 0; t < 4; t++) {
                uint32_t b0f = __float_as_uint(bc[t].x);
                uint32_t b1f = __float_as_uint(bc[t].y);
                #pragma unroll
                for (int i = 0; i < 2; i++)
                    mma_tf32(c[i][t][0], c[i][t][1], c[i][t][2], c[i][t][3],
                             a[i][0], a[i][1], a[i][2], a[i][3], b0f, b1f);
            }

            // ---- khalf 1 (k rows k0+8+t4, k0+12+t4) ----
            #pragma unroll
            for (int i = 0; i < 2; i++) {
                int r = 16 * i + g8;
                a[i][0] = __float_as_uint(hbuf[r][k0 + 8 + t4]);
                a[i][1] = __float_as_uint(hbuf[r + 8][k0 + 8 + t4]);
                a[i][2] = __float_as_uint(hbuf[r][k0 + 12 + t4]);
                a[i][3] = __float_as_uint(hbuf[r + 8][k0 + 12 + t4]);
            }
            #pragma unroll
            for (int t = 0; t < 4; t++) {
                uint32_t b0f = __float_as_uint(bc[t].z);
                uint32_t b1f = __float_as_uint(bc[t].w);
                #pragma unroll
                for (int i = 0; i < 2; i++)
                    mma_tf32(c[i][t][0], c[i][t][1], c[i][t][2], c[i][t][3],
                             a[i][0], a[i][1], a[i][2], a[i][3], b0f, b1f);
            }

            #pragma unroll
            for (int t = 0; t < 4; t++) bc[t] = bn[t];
        }

        __syncthreads();   // all A-frag reads done before overwriting hbuf

        #pragma unroll
        for (int i = 0; i < 2; i++) {
            #pragma unroll
            for (int t = 0; t < 4; t++) {
                int r = 16 * i + g8;
                int n = nbase + 8 * t + 2 * t4;
                *reinterpret_cast<float2*>(&hbuf[r][n])     = make_float2(c[i][t][0], c[i][t][1]);
                *reinterpret_cast<float2*>(&hbuf[r + 8][n]) = make_float2(c[i][t][2], c[i][t][3]);
            }
        }
        ln_silu(L + 1);
    };

    // ---- f_total(yin) -> kcur ----
    auto eval_f = [&]() {
        float w0r[6];
        #pragma unroll
        for (int k = 0; k < 6; k++) w0r[k] = sW0[k * Hn + j];
        float bj = sb0[j];
        #pragma unroll 4
        for (int m = 0; m < Mr; m++) {
            float v = bj;
            v = fmaf(yin[m][0], w0r[0], v);
            v = fmaf(yin[m][1], w0r[1], v);
            v = fmaf(yin[m][2], w0r[2], v);
            v = fmaf(psm[m][0], w0r[3], v);
            v = fmaf(psm[m][1], w0r[4], v);
            v = fmaf(psm[m][2], w0r[5], v);
            hbuf[m][j] = v;
        }
        ln_silu(0);

        hidden_layer(0);
        hidden_layer(1);
        hidden_layer(2);

        // output projection 256->3 + Bloch RHS
        for (int m = wid; m < Mr; m += 8) {
            float s0 = 0.f, s1 = 0.f, s2 = 0.f;
            #pragma unroll
            for (int i = 0; i < Hn / 32; i++) {
                int jj = lane + 32 * i;
                float hv = hbuf[m][jj];
                s0 = fmaf(hv, sWout[jj * 3 + 0], s0);
                s1 = fmaf(hv, sWout[jj * 3 + 1], s1);
                s2 = fmaf(hv, sWout[jj * 3 + 2], s2);
            }
            #pragma unroll
            for (int o = 16; o; o >>= 1) {
                s0 += __shfl_xor_sync(0xFFFFFFFFu, s0, o);
                s1 += __shfl_xor_sync(0xFFFFFFFFu, s1, o);
                s2 += __shfl_xor_sync(0xFFFFFFFFu, s2, o);
            }
            if (lane == 0) {
                float u = yin[m][0], v = yin[m][1], w = yin[m][2];
                float Om = psm[m][0], ga = psm[m][2];
                kcur[m][0] = fmaf(gate, s0 + sbout[0], -ga * u);
                kcur[m][1] = fmaf(gate, s1 + sbout[1], -ga * v - Om * w);
                kcur[m][2] = fmaf(gate, s2 + sbout[2], -2.f * ga * (w + 1.f) + Om * v);
            }
        }
        __syncthreads();
    };

    // ---- RK4 time loop ----
    for (int t = 0; t < Tn - 1; t++) {
        float dt = sts[t + 1] - sts[t];

        if (tid < Mr * 3) {
            int m = tid / 3, c = tid % 3;
            yin[m][c] = ysm[m][c];
        }
        __syncthreads();
        eval_f();
        if (tid < Mr * 3) {
            int m = tid / 3, c = tid % 3;
            float k1 = kcur[m][c];
            kacc[m][c] = k1;
            yin[m][c] = fmaf(0.5f * dt, k1, ysm[m][c]);
        }
        __syncthreads();

        eval_f();
        if (tid < Mr * 3) {
            int m = tid / 3, c = tid % 3;
            float k2 = kcur[m][c];
            kacc[m][c] += 2.f * k2;
            yin[m][c] = fmaf(0.5f * dt, k2, ysm[m][c]);
        }
        __syncthreads();

        eval_f();
        if (tid < Mr * 3) {
            int m = tid / 3, c = tid % 3;
            float k3 = kcur[m][c];
            kacc[m][c] += 2.f * k3;
            yin[m][c] = fmaf(dt, k3, ysm[m][c]);
        }
        __syncthreads();

        eval_f();
        if (tid < Mr * 3) {
            int m = tid / 3, c = tid % 3;
            float ksum = kacc[m][c] + kcur[m][c];
            float yn = fmaf(dt * (1.f / 6.f), ksum, ysm[m][c]);
            ysm[m][c] = yn;
            out[((size_t)(t + 1) * Bn + row0 + m) * 3 + c] = yn;
        }
        __syncthreads();
    }
}

extern "C" void kernel_launch(void* const* d_in, const int* in_sizes, int n_in,
                              void* d_out, int out_size) {
    (void)in_sizes; (void)n_in; (void)out_size;
    const int nW = NLm1 * Hn * Hn;
    pack_wh_kernel<<<(nW + 255) / 256, 256>>>((const float*)d_in[5]);
    pinode_rk4_tc_kernel<<<Bn / Mr, NT>>>(
        (const float*)d_in[0],   // y0
        (const float*)d_in[1],   // t_span
        (const float*)d_in[2],   // params
        (const float*)d_in[3],   // W0
        (const float*)d_in[4],   // b0
        (const float*)d_in[6],   // bh
        (const float*)d_in[7],   // ln_g
        (const float*)d_in[8],   // ln_b
        (const float*)d_in[9],   // Wout
        (const float*)d_in[10],  // bout
        (const float*)d_in[11],  // gate
        (float*)d_out);
}

// round 8
// speedup vs baseline: 4.5631x; 1.2910x over previous
#include <cuda_runtime.h>
#include <cuda_bf16.h>
#include <cstdint>

// PINODEv3 persistent RK4 integrator. Hidden GEMMs in bf16 mma.m16n8k16
// (fp32 accumulate), weights pre-packed in fragment order, activations kept
// as bf16x2 in a conflict-free smem buffer. No syncs inside the K-loop.

constexpr int Bn   = 8192;
constexpr int Tn   = 32;
constexpr int Hn   = 256;
constexpr int NLm1 = 3;
constexpr int Mr   = 32;      // batch rows per CTA
constexpr int NT   = 256;     // 8 warps
constexpr int HP   = Hn + 4;  // fp32 pre-act row stride
constexpr int HPB  = 132;     // bf16x2 words per row (128 + 4 pad; 132%32==4)
#define EPSf 1e-5f

// Packed bf16 weights, fragment order:
// word idx = ((((L*16 + kt)*8 + w)*32 + lane)*4 + t)*2 + word
//   n = w*32 + t*8 + (lane>>2);  k = kt*16 + word*8 + 2*(lane&3)
//   lo = Wh[k][n], hi = Wh[k+1][n]
__device__ uint32_t g_Wp[NLm1 * Hn * Hn / 2];

__device__ __forceinline__ uint32_t pack_bf16x2(float lo, float hi) {
    uint32_t u;
    asm("cvt.rn.bf16x2.f32 %0, %1, %2;" : "=r"(u) : "f"(hi), "f"(lo));
    return u;
}
__device__ __forceinline__ float bf_lo(uint32_t u) { return __uint_as_float(u << 16); }
__device__ __forceinline__ float bf_hi(uint32_t u) { return __uint_as_float(u & 0xFFFF0000u); }

__device__ __forceinline__ void mma_bf16(float& c0, float& c1, float& c2, float& c3,
                                         uint32_t a0, uint32_t a1, uint32_t a2, uint32_t a3,
                                         uint32_t b0, uint32_t b1) {
    asm volatile(
        "mma.sync.aligned.m16n8k16.row.col.f32.bf16.bf16.f32 "
        "{%0,%1,%2,%3}, {%4,%5,%6,%7}, {%8,%9}, {%0,%1,%2,%3};"
        : "+f"(c0), "+f"(c1), "+f"(c2), "+f"(c3)
        : "r"(a0), "r"(a1), "r"(a2), "r"(a3), "r"(b0), "r"(b1));
}

__global__ void pack_wh_kernel(const float* __restrict__ Wh) {
    int i = blockIdx.x * blockDim.x + threadIdx.x;
    if (i >= NLm1 * Hn * Hn / 2) return;
    int word = i & 1;
    int t    = (i >> 1) & 3;
    int lane = (i >> 3) & 31;
    int w    = (i >> 8) & 7;
    int kt   = (i >> 11) & 15;
    int L    = i >> 15;
    int n = w * 32 + t * 8 + (lane >> 2);
    int k = kt * 16 + word * 8 + 2 * (lane & 3);
    float lo = Wh[((size_t)L * Hn + k) * Hn + n];
    float hi = Wh[((size_t)L * Hn + k + 1) * Hn + n];
    g_Wp[i] = pack_bf16x2(lo, hi);
}

__global__ void __launch_bounds__(NT, 2) pinode_rk4_tc_kernel(
    const float* __restrict__ y0,
    const float* __restrict__ t_span,
    const float* __restrict__ params,
    const float* __restrict__ W0,
    const float* __restrict__ b0,
    const float* __restrict__ bh,
    const float* __restrict__ ln_g,
    const float* __restrict__ ln_b,
    const float* __restrict__ Wout,
    const float* __restrict__ bout,
    const float* __restrict__ gatep,
    float* __restrict__ out)
{
    __shared__ float sW0[6 * Hn];
    __shared__ float sb0[Hn];
    __shared__ float sbh[NLm1 * Hn];
    __shared__ float sg[4 * Hn];
    __shared__ float sbt[4 * Hn];
    __shared__ float sWout[Hn * 3];
    __shared__ float sbout[3];
    __shared__ float sts[Tn];
    __shared__ alignas(16) float    hbuf[Mr][HP];    // fp32 pre-activations
    __shared__ alignas(16) uint32_t habf[Mr][HPB];   // bf16x2 activations
    __shared__ float ysm[Mr][3], psm[Mr][3], yin[Mr][3];
    __shared__ float kcur[Mr][3], kacc[Mr][3];
    __shared__ float smu[Mr], srs[Mr];
    __shared__ float sgate;

    const int tid  = threadIdx.x;
    const int lane = tid & 31;
    const int wid  = tid >> 5;
    const int g8   = lane >> 2;
    const int t4   = lane & 3;
    const int row0 = blockIdx.x * Mr;
    const int j    = tid;

    // ---- preload params ----
    for (int i = tid; i < 6 * Hn; i += NT) sW0[i] = W0[i];
    for (int i = tid; i < Hn; i += NT)     sb0[i] = b0[i];
    for (int i = tid; i < NLm1 * Hn; i += NT) sbh[i] = bh[i];
    for (int i = tid; i < 4 * Hn; i += NT) { sg[i] = ln_g[i]; sbt[i] = ln_b[i]; }
    for (int i = tid; i < Hn * 3; i += NT) sWout[i] = Wout[i];
    if (tid < 3)  sbout[tid] = bout[tid];
    if (tid < Tn) sts[tid]  = t_span[tid];
    if (tid == 0) sgate = gatep[0];
    for (int i = tid; i < Mr * 3; i += NT) {
        int m = i / 3, c = i % 3;
        float v = y0[(row0 + m) * 3 + c];
        ysm[m][c] = v;
        psm[m][c] = params[(row0 + m) * 3 + c];
        out[(size_t)(row0 + m) * 3 + c] = v;
    }
    __syncthreads();

    const float gate = sgate;

    // ---- LayerNorm + SiLU: hbuf (fp32 pre-act) -> habf (bf16x2) ----
    auto ln_silu = [&](int Lidx) {
        __syncthreads();
        for (int m = wid; m < Mr; m += 8) {
            float s = 0.f, s2 = 0.f;
            #pragma unroll
            for (int i = 0; i < Hn / 32; i++) {
                float v = hbuf[m][lane + 32 * i];
                s += v;
                s2 = fmaf(v, v, s2);
            }
            #pragma unroll
            for (int o = 16; o; o >>= 1) {
                s  += __shfl_xor_sync(0xFFFFFFFFu, s,  o);
                s2 += __shfl_xor_sync(0xFFFFFFFFu, s2, o);
            }
            if (lane == 0) {
                float mu  = s * (1.f / Hn);
                float var = s2 * (1.f / Hn) - mu * mu;
                smu[m] = mu;
                srs[m] = rsqrtf(var + EPSf);
            }
        }
        __syncthreads();
        // each thread: 2 adjacent columns x 16 rows
        const int c2    = (tid & 127) * 2;
        const int mbase = (tid >> 7) * 16;
        float g0 = sg[Lidx * Hn + c2],     g1 = sg[Lidx * Hn + c2 + 1];
        float q0 = sbt[Lidx * Hn + c2],    q1 = sbt[Lidx * Hn + c2 + 1];
        #pragma unroll 4
        for (int m = mbase; m < mbase + 16; m++) {
            float2 hv = *reinterpret_cast<const float2*>(&hbuf[m][c2]);
            float v0 = fmaf((hv.x - smu[m]) * srs[m], g0, q0);
            float v1 = fmaf((hv.y - smu[m]) * srs[m], g1, q1);
            v0 = v0 / (1.f + __expf(-v0));
            v1 = v1 / (1.f + __expf(-v1));
            habf[m][c2 >> 1] = pack_bf16x2(v0, v1);
        }
        __syncthreads();
    };

    // ---- hidden layer L: hbuf = habf @ Wh[L] + bh[L]; then ln_silu ----
    auto hidden_layer = [&](int L) {
        const int nbase = 32 * wid;
        // per-lane base in packed weights (uint4 units); per-kt stride = 512
        const uint4* Wp = reinterpret_cast<const uint4*>(g_Wp)
                        + ((size_t)((L * 16) * 8 + wid) * 32 + lane) * 2;

        float c[2][4][4];
        #pragma unroll
        for (int t = 0; t < 4; t++) {
            float bA = sbh[L * Hn + nbase + 8 * t + 2 * t4];
            float bB = sbh[L * Hn + nbase + 8 * t + 2 * t4 + 1];
            #pragma unroll
            for (int i = 0; i < 2; i++) {
                c[i][t][0] = bA; c[i][t][1] = bB;
                c[i][t][2] = bA; c[i][t][3] = bB;
            }
        }

        uint4 bc0 = __ldg(Wp), bc1 = __ldg(Wp + 1);
        #pragma unroll 4
        for (int kt = 0; kt < 16; kt++) {
            uint4 bn0, bn1;
            if (kt + 1 < 16) {
                bn0 = __ldg(Wp + (kt + 1) * 512);
                bn1 = __ldg(Wp + (kt + 1) * 512 + 1);
            }
            const int kw = kt * 8;   // word index base in habf

            uint32_t a[2][4];
            #pragma unroll
            for (int i = 0; i < 2; i++) {
                int r = 16 * i + g8;
                a[i][0] = habf[r][kw + t4];
                a[i][1] = habf[r + 8][kw + t4];
                a[i][2] = habf[r][kw + 4 + t4];
                a[i][3] = habf[r + 8][kw + 4 + t4];
            }
            #pragma unroll
            for (int i = 0; i < 2; i++) {
                mma_bf16(c[i][0][0], c[i][0][1], c[i][0][2], c[i][0][3],
                         a[i][0], a[i][1], a[i][2], a[i][3], bc0.x, bc0.y);
                mma_bf16(c[i][1][0], c[i][1][1], c[i][1][2], c[i][1][3],
                         a[i][0], a[i][1], a[i][2], a[i][3], bc0.z, bc0.w);
                mma_bf16(c[i][2][0], c[i][2][1], c[i][2][2], c[i][2][3],
                         a[i][0], a[i][1], a[i][2], a[i][3], bc1.x, bc1.y);
                mma_bf16(c[i][3][0], c[i][3][1], c[i][3][2], c[i][3][3],
                         a[i][0], a[i][1], a[i][2], a[i][3], bc1.z, bc1.w);
            }
            bc0 = bn0; bc1 = bn1;
        }

        // store fp32 pre-activations (hbuf not read during K-loop -> no sync)
        #pragma unroll
        for (int i = 0; i < 2; i++) {
            #pragma unroll
            for (int t = 0; t < 4; t++) {
                int r = 16 * i + g8;
                int n = nbase + 8 * t + 2 * t4;
                *reinterpret_cast<float2*>(&hbuf[r][n])     = make_float2(c[i][t][0], c[i][t][1]);
                *reinterpret_cast<float2*>(&hbuf[r + 8][n]) = make_float2(c[i][t][2], c[i][t][3]);
            }
        }
        ln_silu(L + 1);
    };

    // ---- f_total(yin) -> kcur ----
    auto eval_f = [&]() {
        float w0r[6];
        #pragma unroll
        for (int k = 0; k < 6; k++) w0r[k] = sW0[k * Hn + j];
        float bj = sb0[j];
        #pragma unroll 4
        for (int m = 0; m < Mr; m++) {
            float v = bj;
            v = fmaf(yin[m][0], w0r[0], v);
            v = fmaf(yin[m][1], w0r[1], v);
            v = fmaf(yin[m][2], w0r[2], v);
            v = fmaf(psm[m][0], w0r[3], v);
            v = fmaf(psm[m][1], w0r[4], v);
            v = fmaf(psm[m][2], w0r[5], v);
            hbuf[m][j] = v;
        }
        ln_silu(0);

        hidden_layer(0);
        hidden_layer(1);
        hidden_layer(2);

        // output projection 256->3 (reads bf16 activations) + Bloch RHS
        for (int m = wid; m < Mr; m += 8) {
            float s0 = 0.f, s1 = 0.f, s2 = 0.f;
            #pragma unroll
            for (int i = 0; i < 4; i++) {
                int wI = lane + 32 * i;          // word 0..127 -> cols 2wI, 2wI+1
                uint32_t pw = habf[m][wI];
                float lo = bf_lo(pw), hi = bf_hi(pw);
                s0 = fmaf(lo, sWout[(2 * wI) * 3 + 0], s0);
                s1 = fmaf(lo, sWout[(2 * wI) * 3 + 1], s1);
                s2 = fmaf(lo, sWout[(2 * wI) * 3 + 2], s2);
                s0 = fmaf(hi, sWout[(2 * wI + 1) * 3 + 0], s0);
                s1 = fmaf(hi, sWout[(2 * wI + 1) * 3 + 1], s1);
                s2 = fmaf(hi, sWout[(2 * wI + 1) * 3 + 2], s2);
            }
            #pragma unroll
            for (int o = 16; o; o >>= 1) {
                s0 += __shfl_xor_sync(0xFFFFFFFFu, s0, o);
                s1 += __shfl_xor_sync(0xFFFFFFFFu, s1, o);
                s2 += __shfl_xor_sync(0xFFFFFFFFu, s2, o);
            }
            if (lane == 0) {
                float u = yin[m][0], v = yin[m][1], w = yin[m][2];
                float Om = psm[m][0], ga = psm[m][2];
                kcur[m][0] = fmaf(gate, s0 + sbout[0], -ga * u);
                kcur[m][1] = fmaf(gate, s1 + sbout[1], -ga * v - Om * w);
                kcur[m][2] = fmaf(gate, s2 + sbout[2], -2.f * ga * (w + 1.f) + Om * v);
            }
        }
        __syncthreads();
    };

    // ---- RK4 time loop ----
    for (int t = 0; t < Tn - 1; t++) {
        float dt = sts[t + 1] - sts[t];

        if (tid < Mr * 3) {
            int m = tid / 3, c = tid % 3;
            yin[m][c] = ysm[m][c];
        }
        __syncthreads();
        eval_f();
        if (tid < Mr * 3) {
            int m = tid / 3, c = tid % 3;
            float k1 = kcur[m][c];
            kacc[m][c] = k1;
            yin[m][c] = fmaf(0.5f * dt, k1, ysm[m][c]);
        }
        __syncthreads();

        eval_f();
        if (tid < Mr * 3) {
            int m = tid / 3, c = tid % 3;
            float k2 = kcur[m][c];
            kacc[m][c] += 2.f * k2;
            yin[m][c] = fmaf(0.5f * dt, k2, ysm[m][c]);
        }
        __syncthreads();

        eval_f();
        if (tid < Mr * 3) {
            int m = tid / 3, c = tid % 3;
            float k3 = kcur[m][c];
            kacc[m][c] += 2.f * k3;
            yin[m][c] = fmaf(dt, k3, ysm[m][c]);
        }
        __syncthreads();

        eval_f();
        if (tid < Mr * 3) {
            int m = tid / 3, c = tid % 3;
            float ksum = kacc[m][c] + kcur[m][c];
            float yn = fmaf(dt * (1.f / 6.f), ksum, ysm[m][c]);
            ysm[m][c] = yn;
            out[((size_t)(t + 1) * Bn + row0 + m) * 3 + c] = yn;
        }
        __syncthreads();
    }
}

extern "C" void kernel_launch(void* const* d_in, const int* in_sizes, int n_in,
                              void* d_out, int out_size) {
    (void)in_sizes; (void)n_in; (void)out_size;
    const int nW = NLm1 * Hn * Hn / 2;
    pack_wh_kernel<<<(nW + 255) / 256, 256>>>((const float*)d_in[5]);
    pinode_rk4_tc_kernel<<<Bn / Mr, NT>>>(
        (const float*)d_in[0],   // y0
        (const float*)d_in[1],   // t_span
        (const float*)d_in[2],   // params
        (const float*)d_in[3],   // W0
        (const float*)d_in[4],   // b0
        (const float*)d_in[6],   // bh
        (const float*)d_in[7],   // ln_g
        (const float*)d_in[8],   // ln_b
        (const float*)d_in[9],   // Wout
        (const float*)d_in[10],  // bout
        (const float*)d_in[11],  // gate
        (float*)d_out);
}

// round 9
// speedup vs baseline: 7.2807x; 1.5955x over previous
#include <cuda_runtime.h>
#include <cuda_bf16.h>
#include <cstdint>

// PINODEv3 persistent RK4 integrator. bf16 m16n8k16 hidden GEMMs with
// ldmatrix A-frags, register-fused LayerNorm+SiLU epilogue (no fp32 smem
// round-trip), tanh-based SiLU, RK4 update fused into the output projection.

constexpr int Bn   = 8192;
constexpr int Tn   = 32;
constexpr int Hn   = 256;
constexpr int NLm1 = 3;
constexpr int Mr   = 32;      // batch rows per CTA
constexpr int NT   = 256;     // 8 warps
constexpr int HP   = Hn + 4;  // fp32 layer0 pre-act row stride
constexpr int HPB  = 132;     // bf16x2 words per row (128 + 4 pad)
#define EPSf 1e-5f

// Packed bf16 weights (fragment order), same as R8:
// word idx = ((((L*16 + kt)*8 + w)*32 + lane)*4 + t)*2 + word
__device__ uint32_t g_Wp[NLm1 * Hn * Hn / 2];

__device__ __forceinline__ uint32_t pack_bf16x2(float lo, float hi) {
    uint32_t u;
    asm("cvt.rn.bf16x2.f32 %0, %1, %2;" : "=r"(u) : "f"(hi), "f"(lo));
    return u;
}
__device__ __forceinline__ float bf_lo(uint32_t u) { return __uint_as_float(u << 16); }
__device__ __forceinline__ float bf_hi(uint32_t u) { return __uint_as_float(u & 0xFFFF0000u); }

__device__ __forceinline__ float silu_t(float v) {
    float t;
    asm("tanh.approx.f32 %0, %1;" : "=f"(t) : "f"(0.5f * v));
    return fmaf(0.5f * v, t, 0.5f * v);   // v * sigmoid(v)
}

__device__ __forceinline__ void mma_bf16(float& c0, float& c1, float& c2, float& c3,
                                         uint32_t a0, uint32_t a1, uint32_t a2, uint32_t a3,
                                         uint32_t b0, uint32_t b1) {
    asm volatile(
        "mma.sync.aligned.m16n8k16.row.col.f32.bf16.bf16.f32 "
        "{%0,%1,%2,%3}, {%4,%5,%6,%7}, {%8,%9}, {%0,%1,%2,%3};"
        : "+f"(c0), "+f"(c1), "+f"(c2), "+f"(c3)
        : "r"(a0), "r"(a1), "r"(a2), "r"(a3), "r"(b0), "r"(b1));
}
__device__ __forceinline__ void ldsm_x4(uint32_t addr, uint32_t& r0, uint32_t& r1,
                                        uint32_t& r2, uint32_t& r3) {
    asm volatile("ldmatrix.sync.aligned.m8n8.x4.shared.b16 {%0,%1,%2,%3}, [%4];"
                 : "=r"(r0), "=r"(r1), "=r"(r2), "=r"(r3) : "r"(addr));
}

__global__ void pack_wh_kernel(const float* __restrict__ Wh) {
    int i = blockIdx.x * blockDim.x + threadIdx.x;
    if (i >= NLm1 * Hn * Hn / 2) return;
    int word = i & 1;
    int t    = (i >> 1) & 3;
    int lane = (i >> 3) & 31;
    int w    = (i >> 8) & 7;
    int kt   = (i >> 11) & 15;
    int L    = i >> 15;
    int n = w * 32 + t * 8 + (lane >> 2);
    int k = kt * 16 + word * 8 + 2 * (lane & 3);
    float lo = Wh[((size_t)L * Hn + k) * Hn + n];
    float hi = Wh[((size_t)L * Hn + k + 1) * Hn + n];
    g_Wp[i] = pack_bf16x2(lo, hi);
}

__global__ void __launch_bounds__(NT, 2) pinode_rk4_tc_kernel(
    const float* __restrict__ y0,
    const float* __restrict__ t_span,
    const float* __restrict__ params,
    const float* __restrict__ W0,
    const float* __restrict__ b0,
    const float* __restrict__ bh,
    const float* __restrict__ ln_g,
    const float* __restrict__ ln_b,
    const float* __restrict__ Wout,
    const float* __restrict__ bout,
    const float* __restrict__ gatep,
    float* __restrict__ out)
{
    __shared__ float sW0[6 * Hn];
    __shared__ float sb0[Hn];
    __shared__ float sbh[NLm1 * Hn];
    __shared__ alignas(16) float sg[4 * Hn];
    __shared__ alignas(16) float sbt[4 * Hn];
    __shared__ float sWout[Hn * 3];
    __shared__ float sbout[3];
    __shared__ float sts[Tn];
    __shared__ alignas(16) float    hbuf[Mr][HP];    // layer0 fp32 pre-acts
    __shared__ alignas(16) uint32_t habf[Mr][HPB];   // bf16x2 activations
    __shared__ float pS[Mr][9], pS2[Mr][9];          // LN cross-warp partials
    __shared__ float ysm[Mr][3], psm[Mr][3], yin[Mr][3];
    __shared__ float kacc[Mr][3];
    __shared__ float smu[Mr], srs[Mr];
    __shared__ float sgate;

    const int tid  = threadIdx.x;
    const int lane = tid & 31;
    const int wid  = tid >> 5;
    const int g8   = lane >> 2;
    const int t4   = lane & 3;
    const int row0 = blockIdx.x * Mr;
    const int j    = tid;

    // ldmatrix per-lane A address (i=0 tile); i=1 tile at +16*HPB*4
    const int rowsel = lane & 7;
    const int rhalf  = (lane >> 3) & 1;
    const int khalf  = lane >> 4;
    const uint32_t habf_u32 = (uint32_t)__cvta_generic_to_shared(&habf[0][0]);
    const uint32_t aBase = habf_u32 + (uint32_t)(((8 * rhalf + rowsel) * HPB + 4 * khalf) * 4);

    // ---- preload params ----
    for (int i = tid; i < 6 * Hn; i += NT) sW0[i] = W0[i];
    for (int i = tid; i < Hn; i += NT)     sb0[i] = b0[i];
    for (int i = tid; i < NLm1 * Hn; i += NT) sbh[i] = bh[i];
    for (int i = tid; i < 4 * Hn; i += NT) { sg[i] = ln_g[i]; sbt[i] = ln_b[i]; }
    for (int i = tid; i < Hn * 3; i += NT) sWout[i] = Wout[i];
    if (tid < 3)  sbout[tid] = bout[tid];
    if (tid < Tn) sts[tid]  = t_span[tid];
    if (tid == 0) sgate = gatep[0];
    for (int i = tid; i < Mr * 3; i += NT) {
        int m = i / 3, c = i % 3;
        float v = y0[(row0 + m) * 3 + c];
        ysm[m][c] = v;
        yin[m][c] = v;                       // stage-0 input of step 0
        psm[m][c] = params[(row0 + m) * 3 + c];
        out[(size_t)(row0 + m) * 3 + c] = v;
    }
    __syncthreads();

    const float gate = sgate;

    // ---- layer0 LN+SiLU (hbuf fp32 -> habf bf16x2), smem-based ----
    auto ln_silu0 = [&]() {
        __syncthreads();
        for (int m = wid; m < Mr; m += 8) {
            float s = 0.f, s2 = 0.f;
            #pragma unroll
            for (int i = 0; i < Hn / 32; i++) {
                float v = hbuf[m][lane + 32 * i];
                s += v;
                s2 = fmaf(v, v, s2);
            }
            #pragma unroll
            for (int o = 16; o; o >>= 1) {
                s  += __shfl_xor_sync(0xFFFFFFFFu, s,  o);
                s2 += __shfl_xor_sync(0xFFFFFFFFu, s2, o);
            }
            if (lane == 0) {
                float mu  = s * (1.f / Hn);
                float var = s2 * (1.f / Hn) - mu * mu;
                smu[m] = mu;
                srs[m] = rsqrtf(var + EPSf);
            }
        }
        __syncthreads();
        const int c2    = (tid & 127) * 2;
        const int mbase = (tid >> 7) * 16;
        float g0 = sg[c2], g1 = sg[c2 + 1];
        float q0 = sbt[c2], q1 = sbt[c2 + 1];
        #pragma unroll 4
        for (int m = mbase; m < mbase + 16; m++) {
            float2 hv = *reinterpret_cast<const float2*>(&hbuf[m][c2]);
            float v0 = silu_t(fmaf((hv.x - smu[m]) * srs[m], g0, q0));
            float v1 = silu_t(fmaf((hv.y - smu[m]) * srs[m], g1, q1));
            habf[m][c2 >> 1] = pack_bf16x2(v0, v1);
        }
        __syncthreads();
    };

    // ---- hidden layer L: habf = silu(ln(habf @ Wh[L] + bh[L])) fully fused ----
    auto hidden_layer = [&](int L) {
        const int nbase = 32 * wid;
        const uint4* Wp = reinterpret_cast<const uint4*>(g_Wp)
                        + ((size_t)((L * 16) * 8 + wid) * 32 + lane) * 2;

        float c[2][4][4];
        #pragma unroll
        for (int t = 0; t < 4; t++) {
            float bA = sbh[L * Hn + nbase + 8 * t + 2 * t4];
            float bB = sbh[L * Hn + nbase + 8 * t + 2 * t4 + 1];
            #pragma unroll
            for (int i = 0; i < 2; i++) {
                c[i][t][0] = bA; c[i][t][1] = bB;
                c[i][t][2] = bA; c[i][t][3] = bB;
            }
        }

        uint4 bc0 = __ldg(Wp), bc1 = __ldg(Wp + 1);
        #pragma unroll 4
        for (int kt = 0; kt < 16; kt++) {
            uint4 bn0, bn1;
            if (kt + 1 < 16) {
                bn0 = __ldg(Wp + (kt + 1) * 512);
                bn1 = __ldg(Wp + (kt + 1) * 512 + 1);
            }
            uint32_t a[2][4];
            ldsm_x4(aBase + kt * 32,                 a[0][0], a[0][1], a[0][2], a[0][3]);
            ldsm_x4(aBase + kt * 32 + 16 * HPB * 4,  a[1][0], a[1][1], a[1][2], a[1][3]);
            #pragma unroll
            for (int i = 0; i < 2; i++) {
                mma_bf16(c[i][0][0], c[i][0][1], c[i][0][2], c[i][0][3],
                         a[i][0], a[i][1], a[i][2], a[i][3], bc0.x, bc0.y);
                mma_bf16(c[i][1][0], c[i][1][1], c[i][1][2], c[i][1][3],
                         a[i][0], a[i][1], a[i][2], a[i][3], bc0.z, bc0.w);
                mma_bf16(c[i][2][0], c[i][2][1], c[i][2][2], c[i][2][3],
                         a[i][0], a[i][1], a[i][2], a[i][3], bc1.x, bc1.y);
                mma_bf16(c[i][3][0], c[i][3][1], c[i][3][2], c[i][3][3],
                         a[i][0], a[i][1], a[i][2], a[i][3], bc1.z, bc1.w);
            }
            bc0 = bn0; bc1 = bn1;
        }

        // ---- fused LN epilogue: per-row partials from registers ----
        // lane holds rows r = 16*i + 8*h + g8, cols nbase + 8t + 2*t4 (+1)
        float ps[4], pq[4];
        #pragma unroll
        for (int i = 0; i < 2; i++) {
            #pragma unroll
            for (int h = 0; h < 2; h++) {
                float s = 0.f, s2 = 0.f;
                #pragma unroll
                for (int t = 0; t < 4; t++) {
                    float v0 = c[i][t][2 * h], v1 = c[i][t][2 * h + 1];
                    s += v0 + v1;
                    s2 = fmaf(v0, v0, fmaf(v1, v1, s2));
                }
                s  += __shfl_xor_sync(0xFFFFFFFFu, s, 1);
                s  += __shfl_xor_sync(0xFFFFFFFFu, s, 2);
                s2 += __shfl_xor_sync(0xFFFFFFFFu, s2, 1);
                s2 += __shfl_xor_sync(0xFFFFFFFFu, s2, 2);
                ps[2 * i + h] = s;
                pq[2 * i + h] = s2;
            }
        }
        if (t4 == 0) {
            #pragma unroll
            for (int q = 0; q < 4; q++) {
                int r = 16 * (q >> 1) + 8 * (q & 1) + g8;
                pS[r][wid]  = ps[q];
                pS2[r][wid] = pq[q];
            }
        }
        __syncthreads();
        if (tid < Mr) {
            float s = 0.f, s2 = 0.f;
            #pragma unroll
            for (int w = 0; w < 8; w++) { s += pS[tid][w]; s2 += pS2[tid][w]; }
            float mu  = s * (1.f / Hn);
            float var = s2 * (1.f / Hn) - mu * mu;
            smu[tid] = mu;
            srs[tid] = rsqrtf(var + EPSf);
        }
        __syncthreads();

        // apply LN+SiLU on registers, pack to habf
        const int Lh = L + 1;
        float2 gv[4], bv[4];
        #pragma unroll
        for (int t = 0; t < 4; t++) {
            gv[t] = *reinterpret_cast<const float2*>(&sg[Lh * Hn + nbase + 8 * t + 2 * t4]);
            bv[t] = *reinterpret_cast<const float2*>(&sbt[Lh * Hn + nbase + 8 * t + 2 * t4]);
        }
        #pragma unroll
        for (int i = 0; i < 2; i++) {
            #pragma unroll
            for (int h = 0; h < 2; h++) {
                int r = 16 * i + 8 * h + g8;
                float mu = smu[r], rs = srs[r];
                #pragma unroll
                for (int t = 0; t < 4; t++) {
                    float v0 = silu_t(fmaf((c[i][t][2 * h]     - mu) * rs, gv[t].x, bv[t].x));
                    float v1 = silu_t(fmaf((c[i][t][2 * h + 1] - mu) * rs, gv[t].y, bv[t].y));
                    habf[r][16 * wid + 4 * t + t4] = pack_bf16x2(v0, v1);
                }
            }
        }
        __syncthreads();
    };

    // ---- output projection + Bloch RHS + fused RK4 stage update ----
    auto outproj_update = [&](int stage, float dt) {
        for (int m = wid; m < Mr; m += 8) {
            float s0 = 0.f, s1 = 0.f, s2 = 0.f;
            #pragma unroll
            for (int i = 0; i < 4; i++) {
                int wI = lane + 32 * i;
                uint32_t pw = habf[m][wI];
                float lo = bf_lo(pw), hi = bf_hi(pw);
                s0 = fmaf(lo, sWout[(2 * wI) * 3 + 0], s0);
                s1 = fmaf(lo, sWout[(2 * wI) * 3 + 1], s1);
                s2 = fmaf(lo, sWout[(2 * wI) * 3 + 2], s2);
                s0 = fmaf(hi, sWout[(2 * wI + 1) * 3 + 0], s0);
                s1 = fmaf(hi, sWout[(2 * wI + 1) * 3 + 1], s1);
                s2 = fmaf(hi, sWout[(2 * wI + 1) * 3 + 2], s2);
            }
            #pragma unroll
            for (int o = 16; o; o >>= 1) {
                s0 += __shfl_xor_sync(0xFFFFFFFFu, s0, o);
                s1 += __shfl_xor_sync(0xFFFFFFFFu, s1, o);
                s2 += __shfl_xor_sync(0xFFFFFFFFu, s2, o);
            }
            if (lane == 0) {
                float u = yin[m][0], v = yin[m][1], w = yin[m][2];
                float Om = psm[m][0], ga = psm[m][2];
                float k0 = fmaf(gate, s0 + sbout[0], -ga * u);
                float k1 = fmaf(gate, s1 + sbout[1], -ga * v - Om * w);
                float k2 = fmaf(gate, s2 + sbout[2], -2.f * ga * (w + 1.f) + Om * v);
                float ya = ysm[m][0], yb = ysm[m][1], yc = ysm[m][2];
                if (stage == 0) {
                    kacc[m][0] = k0; kacc[m][1] = k1; kacc[m][2] = k2;
                    yin[m][0] = fmaf(0.5f * dt, k0, ya);
                    yin[m][1] = fmaf(0.5f * dt, k1, yb);
                    yin[m][2] = fmaf(0.5f * dt, k2, yc);
                } else if (stage == 1) {
                    kacc[m][0] += 2.f * k0; kacc[m][1] += 2.f * k1; kacc[m][2] += 2.f * k2;
                    yin[m][0] = fmaf(0.5f * dt, k0, ya);
                    yin[m][1] = fmaf(0.5f * dt, k1, yb);
                    yin[m][2] = fmaf(0.5f * dt, k2, yc);
                } else if (stage == 2) {
                    kacc[m][0] += 2.f * k0; kacc[m][1] += 2.f * k1; kacc[m][2] += 2.f * k2;
                    yin[m][0] = fmaf(dt, k0, ya);
                    yin[m][1] = fmaf(dt, k1, yb);
                    yin[m][2] = fmaf(dt, k2, yc);
                }
                // stage 3 handled by caller (needs t index for the store)
                else {
                    float c6 = dt * (1.f / 6.f);
                    float y0n = fmaf(c6, kacc[m][0] + k0, ya);
                    float y1n = fmaf(c6, kacc[m][1] + k1, yb);
                    float y2n = fmaf(c6, kacc[m][2] + k2, yc);
                    ysm[m][0] = y0n; ysm[m][1] = y1n; ysm[m][2] = y2n;
                    yin[m][0] = y0n; yin[m][1] = y1n; yin[m][2] = y2n;
                    kacc[m][0] = y0n; kacc[m][1] = y1n; kacc[m][2] = y2n; // reuse as store buf
                }
            }
        }
        __syncthreads();
    };

    // ---- f_total(yin) + stage update ----
    auto eval_f = [&](int stage, float dt) {
        float w0r[6];
        #pragma unroll
        for (int k = 0; k < 6; k++) w0r[k] = sW0[k * Hn + j];
        float bj = sb0[j];
        #pragma unroll 4
        for (int m = 0; m < Mr; m++) {
            float v = bj;
            v = fmaf(yin[m][0], w0r[0], v);
            v = fmaf(yin[m][1], w0r[1], v);
            v = fmaf(yin[m][2], w0r[2], v);
            v = fmaf(psm[m][0], w0r[3], v);
            v = fmaf(psm[m][1], w0r[4], v);
            v = fmaf(psm[m][2], w0r[5], v);
            hbuf[m][j] = v;
        }
        ln_silu0();
        hidden_layer(0);
        hidden_layer(1);
        hidden_layer(2);
        outproj_update(stage, dt);
    };

    // ---- RK4 time loop ----
    for (int t = 0; t < Tn - 1; t++) {
        float dt = sts[t + 1] - sts[t];
        eval_f(0, dt);
        eval_f(1, dt);
        eval_f(2, dt);
        eval_f(3, dt);
        // store y_{t+1}
        for (int i = tid; i < Mr * 3; i += NT) {
            int m = i / 3, c = i % 3;
            out[((size_t)(t + 1) * Bn + row0 + m) * 3 + c] = kacc[m][c];
        }
        // no barrier needed: kacc not rewritten until next stage-0 update,
        // which is separated by the outproj barrier of stage 0... but kacc IS
        // written at next stage-0 by lane0 after its __syncthreads-guarded
        // outproj; the store above races with that write. Add one barrier:
        __syncthreads();
    }
}

extern "C" void kernel_launch(void* const* d_in, const int* in_sizes, int n_in,
                              void* d_out, int out_size) {
    (void)in_sizes; (void)n_in; (void)out_size;
    const int nW = NLm1 * Hn * Hn / 2;
    pack_wh_kernel<<<(nW + 255) / 256, 256>>>((const float*)d_in[5]);
    pinode_rk4_tc_kernel<<<Bn / Mr, NT>>>(
        (const float*)d_in[0],   // y0
        (const float*)d_in[1],   // t_span
        (const float*)d_in[2],   // params
        (const float*)d_in[3],   // W0
        (const float*)d_in[4],   // b0
        (const float*)d_in[6],   // bh
        (const float*)d_in[7],   // ln_g
        (const float*)d_in[8],   // ln_b
        (const float*)d_in[9],   // Wout
        (const float*)d_in[10],  // bout
        (const float*)d_in[11],  // gate
        (float*)d_out);
}

// round 11
// speedup vs baseline: 8.0013x; 1.0990x over previous
#include <cuda_runtime.h>
#include <cuda_bf16.h>
#include <cstdint>

// PINODEv3 persistent RK4 integrator. bf16 m16n8k16 hidden GEMMs, ldmatrix
// A-frags software-pipelined by one k-tile, layer0 computed directly in mma
// fragment layout (no fp32 smem round-trip anywhere), register-fused LN+SiLU
// epilogue, stage-parametrized RK4 (single code copy of the eval body).

constexpr int Bn   = 8192;
constexpr int Tn   = 32;
constexpr int Hn   = 256;
constexpr int NLm1 = 3;
constexpr int Mr   = 32;      // batch rows per CTA
constexpr int NT   = 256;     // 8 warps
constexpr int HPB  = 132;     // bf16x2 words per activation row (128 + 4 pad)
#define EPSf 1e-5f

// Packed bf16 weights (fragment order), same as R8/R9:
// word idx = ((((L*16 + kt)*8 + w)*32 + lane)*4 + t)*2 + word
__device__ uint32_t g_Wp[NLm1 * Hn * Hn / 2];

__device__ __forceinline__ uint32_t pack_bf16x2(float lo, float hi) {
    uint32_t u;
    asm("cvt.rn.bf16x2.f32 %0, %1, %2;" : "=r"(u) : "f"(hi), "f"(lo));
    return u;
}
__device__ __forceinline__ float bf_lo(uint32_t u) { return __uint_as_float(u << 16); }
__device__ __forceinline__ float bf_hi(uint32_t u) { return __uint_as_float(u & 0xFFFF0000u); }

__device__ __forceinline__ float silu_t(float v) {
    float t;
    asm("tanh.approx.f32 %0, %1;" : "=f"(t) : "f"(0.5f * v));
    return fmaf(0.5f * v, t, 0.5f * v);   // v * sigmoid(v)
}

__device__ __forceinline__ void mma_bf16(float& c0, float& c1, float& c2, float& c3,
                                         uint32_t a0, uint32_t a1, uint32_t a2, uint32_t a3,
                                         uint32_t b0, uint32_t b1) {
    asm volatile(
        "mma.sync.aligned.m16n8k16.row.col.f32.bf16.bf16.f32 "
        "{%0,%1,%2,%3}, {%4,%5,%6,%7}, {%8,%9}, {%0,%1,%2,%3};"
        : "+f"(c0), "+f"(c1), "+f"(c2), "+f"(c3)
        : "r"(a0), "r"(a1), "r"(a2), "r"(a3), "r"(b0), "r"(b1));
}
__device__ __forceinline__ void ldsm_x4(uint32_t addr, uint32_t& r0, uint32_t& r1,
                                        uint32_t& r2, uint32_t& r3) {
    asm volatile("ldmatrix.sync.aligned.m8n8.x4.shared.b16 {%0,%1,%2,%3}, [%4];"
                 : "=r"(r0), "=r"(r1), "=r"(r2), "=r"(r3) : "r"(addr));
}

__global__ void pack_wh_kernel(const float* __restrict__ Wh) {
    int i = blockIdx.x * blockDim.x + threadIdx.x;
    if (i >= NLm1 * Hn * Hn / 2) return;
    int word = i & 1;
    int t    = (i >> 1) & 3;
    int lane = (i >> 3) & 31;
    int w    = (i >> 8) & 7;
    int kt   = (i >> 11) & 15;
    int L    = i >> 15;
    int n = w * 32 + t * 8 + (lane >> 2);
    int k = kt * 16 + word * 8 + 2 * (lane & 3);
    float lo = Wh[((size_t)L * Hn + k) * Hn + n];
    float hi = Wh[((size_t)L * Hn + k + 1) * Hn + n];
    g_Wp[i] = pack_bf16x2(lo, hi);
}

__global__ void __launch_bounds__(NT, 2) pinode_rk4_tc_kernel(
    const float* __restrict__ y0,
    const float* __restrict__ t_span,
    const float* __restrict__ params,
    const float* __restrict__ W0,
    const float* __restrict__ b0,
    const float* __restrict__ bh,
    const float* __restrict__ ln_g,
    const float* __restrict__ ln_b,
    const float* __restrict__ Wout,
    const float* __restrict__ bout,
    const float* __restrict__ gatep,
    float* __restrict__ out)
{
    __shared__ alignas(16) float sW0[6 * Hn];
    __shared__ alignas(16) float sb0[Hn];
    __shared__ alignas(16) float sbh[NLm1 * Hn];
    __shared__ alignas(16) float sg[4 * Hn];
    __shared__ alignas(16) float sbt[4 * Hn];
    __shared__ float sWout[Hn * 3];
    __shared__ float sbout[3];
    __shared__ float sts[Tn];
    __shared__ alignas(16) uint32_t habf[Mr][HPB];   // bf16x2 activations
    __shared__ alignas(8) float2 pSv[Mr][9];         // LN cross-warp partials
    __shared__ float ysm[Mr][3], psm[Mr][3], yin[Mr][3];
    __shared__ float kacc[Mr][3];
    __shared__ float smu[Mr], srs[Mr];
    __shared__ float sgate;

    const int tid  = threadIdx.x;
    const int lane = tid & 31;
    const int wid  = tid >> 5;
    const int g8   = lane >> 2;
    const int t4   = lane & 3;
    const int row0 = blockIdx.x * Mr;
    const int nbase = 32 * wid;

    // ldmatrix per-lane A address (i=0 tile); i=1 tile at +16*HPB*4
    const int rowsel = lane & 7;
    const int rhalf  = (lane >> 3) & 1;
    const int khalf  = lane >> 4;
    const uint32_t habf_u32 = (uint32_t)__cvta_generic_to_shared(&habf[0][0]);
    const uint32_t aBase = habf_u32 + (uint32_t)(((8 * rhalf + rowsel) * HPB + 4 * khalf) * 4);

    // ---- preload params ----
    for (int i = tid; i < 6 * Hn; i += NT) sW0[i] = W0[i];
    for (int i = tid; i < Hn; i += NT)     sb0[i] = b0[i];
    for (int i = tid; i < NLm1 * Hn; i += NT) sbh[i] = bh[i];
    for (int i = tid; i < 4 * Hn; i += NT) { sg[i] = ln_g[i]; sbt[i] = ln_b[i]; }
    for (int i = tid; i < Hn * 3; i += NT) sWout[i] = Wout[i];
    if (tid < 3)  sbout[tid] = bout[tid];
    if (tid < Tn) sts[tid]  = t_span[tid];
    if (tid == 0) sgate = gatep[0];
    for (int i = tid; i < Mr * 3; i += NT) {
        int m = i / 3, c = i % 3;
        float v = y0[(row0 + m) * 3 + c];
        ysm[m][c] = v;
        yin[m][c] = v;
        psm[m][c] = params[(row0 + m) * 3 + c];
        out[(size_t)(row0 + m) * 3 + c] = v;
    }
    __syncthreads();

    const float gate = sgate;

    // ---- fused LN + SiLU epilogue on C fragments -> habf (bf16x2) ----
    // lnrow: which ln_g/ln_b row to use.
    auto fused_ln_epi = [&](float (&c)[2][4][4], int lnrow) {
        // per-row partial sums from registers (quad reduction over t4)
        #pragma unroll
        for (int q = 0; q < 4; q++) {
            int i = q >> 1, h = q & 1;
            float s = 0.f, s2 = 0.f;
            #pragma unroll
            for (int t = 0; t < 4; t++) {
                float v0 = c[i][t][2 * h], v1 = c[i][t][2 * h + 1];
                s += v0 + v1;
                s2 = fmaf(v0, v0, fmaf(v1, v1, s2));
            }
            s  += __shfl_xor_sync(0xFFFFFFFFu, s, 1);
            s  += __shfl_xor_sync(0xFFFFFFFFu, s, 2);
            s2 += __shfl_xor_sync(0xFFFFFFFFu, s2, 1);
            s2 += __shfl_xor_sync(0xFFFFFFFFu, s2, 2);
            if (t4 == 0) {
                int r = 16 * i + 8 * h + g8;
                pSv[r][wid] = make_float2(s, s2);
            }
        }
        __syncthreads();
        if (tid < Mr) {
            float s = 0.f, s2 = 0.f;
            #pragma unroll
            for (int w = 0; w < 8; w++) {
                float2 p = pSv[tid][w];
                s += p.x; s2 += p.y;
            }
            float mu  = s * (1.f / Hn);
            float var = s2 * (1.f / Hn) - mu * mu;
            smu[tid] = mu;
            srs[tid] = rsqrtf(var + EPSf);
        }
        __syncthreads();
        float2 gv[4], bv[4];
        #pragma unroll
        for (int t = 0; t < 4; t++) {
            gv[t] = *reinterpret_cast<const float2*>(&sg[lnrow * Hn + nbase + 8 * t + 2 * t4]);
            bv[t] = *reinterpret_cast<const float2*>(&sbt[lnrow * Hn + nbase + 8 * t + 2 * t4]);
        }
        #pragma unroll
        for (int q = 0; q < 4; q++) {
            int i = q >> 1, h = q & 1;
            int r = 16 * i + 8 * h + g8;
            float mu = smu[r], rs = srs[r];
            #pragma unroll
            for (int t = 0; t < 4; t++) {
                float v0 = silu_t(fmaf((c[i][t][2 * h]     - mu) * rs, gv[t].x, bv[t].x));
                float v1 = silu_t(fmaf((c[i][t][2 * h + 1] - mu) * rs, gv[t].y, bv[t].y));
                habf[r][16 * wid + 4 * t + t4] = pack_bf16x2(v0, v1);
            }
        }
        __syncthreads();
    };

    // ---- one f_total eval + RK4 stage update (stage in 0..3) ----
    auto eval_f = [&](int stage, float dt, int t) {
        float c[2][4][4];

        // ===== layer 0 in fragment layout: C = [y,p] @ W0 + b0 =====
        #pragma unroll
        for (int t_ = 0; t_ < 4; t_++) {
            float2 bb = *reinterpret_cast<const float2*>(&sb0[nbase + 8 * t_ + 2 * t4]);
            c[0][t_][0] = bb.x; c[0][t_][1] = bb.y;
            c[0][t_][2] = bb.x; c[0][t_][3] = bb.y;
            c[1][t_][0] = bb.x; c[1][t_][1] = bb.y;
            c[1][t_][2] = bb.x; c[1][t_][3] = bb.y;
        }
        #pragma unroll
        for (int k = 0; k < 6; k++) {
            float xv[4];
            #pragma unroll
            for (int q = 0; q < 4; q++) {
                int r = 16 * (q >> 1) + 8 * (q & 1) + g8;
                xv[q] = (k < 3) ? yin[r][k] : psm[r][k - 3];
            }
            #pragma unroll
            for (int t_ = 0; t_ < 4; t_++) {
                float2 wv = *reinterpret_cast<const float2*>(&sW0[k * Hn + nbase + 8 * t_ + 2 * t4]);
                #pragma unroll
                for (int q = 0; q < 4; q++) {
                    int i = q >> 1, h = q & 1;
                    c[i][t_][2 * h]     = fmaf(xv[q], wv.x, c[i][t_][2 * h]);
                    c[i][t_][2 * h + 1] = fmaf(xv[q], wv.y, c[i][t_][2 * h + 1]);
                }
            }
        }
        fused_ln_epi(c, 0);

        // ===== hidden layers =====
        #pragma unroll 1
        for (int L = 0; L < NLm1; L++) {
            const uint4* Wp = reinterpret_cast<const uint4*>(g_Wp)
                            + ((size_t)((L * 16) * 8 + wid) * 32 + lane) * 2;
            #pragma unroll
            for (int t_ = 0; t_ < 4; t_++) {
                float2 bb = *reinterpret_cast<const float2*>(&sbh[L * Hn + nbase + 8 * t_ + 2 * t4]);
                c[0][t_][0] = bb.x; c[0][t_][1] = bb.y;
                c[0][t_][2] = bb.x; c[0][t_][3] = bb.y;
                c[1][t_][0] = bb.x; c[1][t_][1] = bb.y;
                c[1][t_][2] = bb.x; c[1][t_][3] = bb.y;
            }

            uint32_t acur[2][4], anext[2][4];
            uint4 bc0 = __ldg(Wp), bc1 = __ldg(Wp + 1);
            ldsm_x4(aBase,                acur[0][0], acur[0][1], acur[0][2], acur[0][3]);
            ldsm_x4(aBase + 16 * HPB * 4, acur[1][0], acur[1][1], acur[1][2], acur[1][3]);

            #pragma unroll
            for (int kt = 0; kt < 16; kt++) {
                uint4 bn0, bn1;
                if (kt + 1 < 16) {
                    bn0 = __ldg(Wp + (kt + 1) * 512);
                    bn1 = __ldg(Wp + (kt + 1) * 512 + 1);
                    ldsm_x4(aBase + (kt + 1) * 32,
                            anext[0][0], anext[0][1], anext[0][2], anext[0][3]);
                    ldsm_x4(aBase + (kt + 1) * 32 + 16 * HPB * 4,
                            anext[1][0], anext[1][1], anext[1][2], anext[1][3]);
                }
                #pragma unroll
                for (int i = 0; i < 2; i++) {
                    mma_bf16(c[i][0][0], c[i][0][1], c[i][0][2], c[i][0][3],
                             acur[i][0], acur[i][1], acur[i][2], acur[i][3], bc0.x, bc0.y);
                    mma_bf16(c[i][1][0], c[i][1][1], c[i][1][2], c[i][1][3],
                             acur[i][0], acur[i][1], acur[i][2], acur[i][3], bc0.z, bc0.w);
                    mma_bf16(c[i][2][0], c[i][2][1], c[i][2][2], c[i][2][3],
                             acur[i][0], acur[i][1], acur[i][2], acur[i][3], bc1.x, bc1.y);
                    mma_bf16(c[i][3][0], c[i][3][1], c[i][3][2], c[i][3][3],
                             acur[i][0], acur[i][1], acur[i][2], acur[i][3], bc1.z, bc1.w);
                }
                if (kt + 1 < 16) {
                    #pragma unroll
                    for (int i = 0; i < 2; i++)
                        #pragma unroll
                        for (int e = 0; e < 4; e++) acur[i][e] = anext[i][e];
                    bc0 = bn0; bc1 = bn1;
                }
            }
            fused_ln_epi(c, L + 1);
        }

        // ===== output projection + Bloch RHS + RK4 stage update =====
        for (int m = wid; m < Mr; m += 8) {
            float s0 = 0.f, s1 = 0.f, s2 = 0.f;
            #pragma unroll
            for (int i = 0; i < 4; i++) {
                int wI = lane + 32 * i;
                uint32_t pw = habf[m][wI];
                float lo = bf_lo(pw), hi = bf_hi(pw);
                s0 = fmaf(lo, sWout[(2 * wI) * 3 + 0], s0);
                s1 = fmaf(lo, sWout[(2 * wI) * 3 + 1], s1);
                s2 = fmaf(lo, sWout[(2 * wI) * 3 + 2], s2);
                s0 = fmaf(hi, sWout[(2 * wI + 1) * 3 + 0], s0);
                s1 = fmaf(hi, sWout[(2 * wI + 1) * 3 + 1], s1);
                s2 = fmaf(hi, sWout[(2 * wI + 1) * 3 + 2], s2);
            }
            #pragma unroll
            for (int o = 16; o; o >>= 1) {
                s0 += __shfl_xor_sync(0xFFFFFFFFu, s0, o);
                s1 += __shfl_xor_sync(0xFFFFFFFFu, s1, o);
                s2 += __shfl_xor_sync(0xFFFFFFFFu, s2, o);
            }
            if (lane == 0) {
                float u = yin[m][0], v = yin[m][1], w = yin[m][2];
                float Om = psm[m][0], ga = psm[m][2];
                float k0 = fmaf(gate, s0 + sbout[0], -ga * u);
                float k1 = fmaf(gate, s1 + sbout[1], -ga * v - Om * w);
                float k2 = fmaf(gate, s2 + sbout[2], -2.f * ga * (w + 1.f) + Om * v);
                float ya = ysm[m][0], yb = ysm[m][1], yc = ysm[m][2];
                if (stage < 3) {
                    if (stage == 0) {
                        kacc[m][0] = k0; kacc[m][1] = k1; kacc[m][2] = k2;
                    } else {
                        kacc[m][0] += 2.f * k0; kacc[m][1] += 2.f * k1; kacc[m][2] += 2.f * k2;
                    }
                    float f = (stage == 2) ? dt : 0.5f * dt;
                    yin[m][0] = fmaf(f, k0, ya);
                    yin[m][1] = fmaf(f, k1, yb);
                    yin[m][2] = fmaf(f, k2, yc);
                } else {
                    float c6 = dt * (1.f / 6.f);
                    float y0n = fmaf(c6, kacc[m][0] + k0, ya);
                    float y1n = fmaf(c6, kacc[m][1] + k1, yb);
                    float y2n = fmaf(c6, kacc[m][2] + k2, yc);
                    ysm[m][0] = y0n; ysm[m][1] = y1n; ysm[m][2] = y2n;
                    yin[m][0] = y0n; yin[m][1] = y1n; yin[m][2] = y2n;
                    size_t idx = ((size_t)(t + 1) * Bn + row0 + m) * 3;
                    out[idx] = y0n; out[idx + 1] = y1n; out[idx + 2] = y2n;
                }
            }
        }
        __syncthreads();
    };

    // ---- RK4 time loop ----
    #pragma unroll 1
    for (int t = 0; t < Tn - 1; t++) {
        float dt = sts[t + 1] - sts[t];
        #pragma unroll 1
        for (int s = 0; s < 4; s++) eval_f(s, dt, t);
    }
}

extern "C" void kernel_launch(void* const* d_in, const int* in_sizes, int n_in,
                              void* d_out, int out_size) {
    (void)in_sizes; (void)n_in; (void)out_size;
    const int nW = NLm1 * Hn * Hn / 2;
    pack_wh_kernel<<<(nW + 255) / 256, 256>>>((const float*)d_in[5]);
    pinode_rk4_tc_kernel<<<Bn / Mr, NT>>>(
        (const float*)d_in[0],   // y0
        (const float*)d_in[1],   // t_span
        (const float*)d_in[2],   // params
        (const float*)d_in[3],   // W0
        (const float*)d_in[4],   // b0
        (const float*)d_in[6],   // bh
        (const float*)d_in[7],   // ln_g
        (const float*)d_in[8],   // ln_b
        (const float*)d_in[9],   // Wout
        (const float*)d_in[10],  // bout
        (const float*)d_in[11],  // gate
        (float*)d_out);
}